// round 2
// baseline (speedup 1.0000x reference)
#include <cuda_runtime.h>
#include <math.h>

#define TD 1024     // hidden dim D
#define TE 64       // experts E
#define BM 64       // tokens per gemm block
#define BK 32       // k-chunk
#define SPLIT 4
#define KS (TD / SPLIT)   // 256 k per block
#define TMAX 16384

typedef unsigned long long ull;

// split-K partial logits: [token][split][expert], 16 MB
__device__ float g_partial[(size_t)TMAX * SPLIT * TE];

__device__ __forceinline__ ull pack2(float lo, float hi) {
    ull r; asm("mov.b64 %0, {%1, %2};" : "=l"(r) : "f"(lo), "f"(hi)); return r;
}
__device__ __forceinline__ void unpack2(ull v, float& lo, float& hi) {
    asm("mov.b64 {%0, %1}, %2;" : "=f"(lo), "=f"(hi) : "l"(v));
}
__device__ __forceinline__ void ffma2(ull& d, ull a, ull b) {
    asm("fma.rn.f32x2 %0, %1, %2, %0;" : "+l"(d) : "l"(a), "l"(b));
}

// ---------------- GEMM: logits partial = X[64tok, KS] @ W^T[KS, 64exp] ----------------
__global__ void __launch_bounds__(128) gate_gemm(
    const float* __restrict__ x,      // [T, D]
    const float* __restrict__ gw)     // [E, D]
{
    // XOR-swizzled, stride-64 (no pad): elem (k, r) at  k*64 + ((r>>2 ^ (k>>2)&7)<<2) + (r&3)
    __shared__ __align__(16) float Xs[BK * 64];
    __shared__ __align__(16) float Ws[BK * 64];

    const int tid = threadIdx.x;
    const int tx = tid & 15;            // expert group: experts tx*4..+3
    const int ty = tid >> 4;            // token group:  tokens  ty*8..+7
    const long long t0 = (long long)blockIdx.x * BM;
    const int kbase = blockIdx.y * KS;

    ull acc[4][4];
    #pragma unroll
    for (int i = 0; i < 4; i++)
        #pragma unroll
        for (int j = 0; j < 4; j++) acc[i][j] = 0ull;

    // register prefetch of chunk 0 (4 float4 X + 4 float4 W per thread)
    float4 xr[4], wr[4];
    #pragma unroll
    for (int i = 0; i < 4; i++) {
        int idx = i * 128 + tid;        // 0..511
        int row = idx >> 3;             // 0..63 (token / expert)
        int c4  = idx & 7;              // float4 index along k-chunk
        xr[i] = *reinterpret_cast<const float4*>(x  + (t0 + row) * TD + kbase + c4 * 4);
        wr[i] = *reinterpret_cast<const float4*>(gw + (long long)row * TD + kbase + c4 * 4);
    }

    for (int k0 = 0; k0 < KS; k0 += BK) {
        __syncthreads();
        // conflict-free swizzled transpose stores
        #pragma unroll
        for (int i = 0; i < 4; i++) {
            int idx = i * 128 + tid;
            int row = idx >> 3;
            int c4  = idx & 7;
            int sw  = (row >> 2) ^ c4;  // c4 == (kk>>2)&7 for kk = c4*4+j
            int wi  = row & 3;
            int base = (c4 * 4) * 64 + sw * 4 + wi;
            Xs[base       ] = xr[i].x;
            Xs[base +   64] = xr[i].y;
            Xs[base + 2*64] = xr[i].z;
            Xs[base + 3*64] = xr[i].w;
            Ws[base       ] = wr[i].x;
            Ws[base +   64] = wr[i].y;
            Ws[base + 2*64] = wr[i].z;
            Ws[base + 3*64] = wr[i].w;
        }
        __syncthreads();
        if (k0 + BK < KS) {             // prefetch next chunk
            #pragma unroll
            for (int i = 0; i < 4; i++) {
                int idx = i * 128 + tid;
                int row = idx >> 3;
                int c4  = idx & 7;
                xr[i] = *reinterpret_cast<const float4*>(x  + (t0 + row) * TD + kbase + k0 + BK + c4 * 4);
                wr[i] = *reinterpret_cast<const float4*>(gw + (long long)row * TD + kbase + k0 + BK + c4 * 4);
            }
        }
        #pragma unroll
        for (int k = 0; k < BK; k++) {
            const int s = (k >> 2) & 7;
            ulonglong2 a01 = *reinterpret_cast<const ulonglong2*>(
                Xs + k * 64 + ((((2 * ty + 0) ^ s)) << 2));
            ulonglong2 a23 = *reinterpret_cast<const ulonglong2*>(
                Xs + k * 64 + ((((2 * ty + 1) ^ s)) << 2));
            float4 b4 = *reinterpret_cast<const float4*>(
                Ws + k * 64 + ((tx ^ s) << 2));
            ull a2[4] = { a01.x, a01.y, a23.x, a23.y };
            ull b2[4] = { pack2(b4.x, b4.x), pack2(b4.y, b4.y),
                          pack2(b4.z, b4.z), pack2(b4.w, b4.w) };
            #pragma unroll
            for (int i = 0; i < 4; i++)
                #pragma unroll
                for (int j = 0; j < 4; j++)
                    ffma2(acc[i][j], a2[i], b2[j]);
        }
    }

    // write partial logits (coalesced 256B rows)
    #pragma unroll
    for (int i = 0; i < 4; i++) {
        int m = ty * 8 + 2 * i;
        float4 fa, fb;
        unpack2(acc[i][0], fa.x, fb.x);
        unpack2(acc[i][1], fa.y, fb.y);
        unpack2(acc[i][2], fa.z, fb.z);
        unpack2(acc[i][3], fa.w, fb.w);
        size_t b0 = ((size_t)(t0 + m)     * SPLIT + blockIdx.y) * TE + tx * 4;
        size_t b1 = ((size_t)(t0 + m + 1) * SPLIT + blockIdx.y) * TE + tx * 4;
        *reinterpret_cast<float4*>(g_partial + b0) = fa;
        *reinterpret_cast<float4*>(g_partial + b1) = fb;
    }
}

// ---------------- Epilogue: reduce splits + noise + top-2 + softmax scatter ----------------
__global__ void __launch_bounds__(256) gate_epilogue(
    const float* __restrict__ nw,     // [E]
    const float* __restrict__ noise,  // [T, E]
    float* __restrict__ out,          // [T*E weights][T*2 idx]
    int T, int write_idx)
{
    __shared__ float nws[TE];
    const int tid = threadIdx.x;
    if (tid < TE) nws[tid] = nw[tid];
    __syncthreads();

    const long long t = (long long)blockIdx.x * 256 + tid;

    float4 l4[16];
    const float4* p = reinterpret_cast<const float4*>(g_partial + (size_t)t * SPLIT * TE);
    #pragma unroll
    for (int j = 0; j < 16; j++) l4[j] = p[j];
    #pragma unroll
    for (int s = 1; s < SPLIT; s++) {
        #pragma unroll
        for (int j = 0; j < 16; j++) {
            float4 q = p[s * 16 + j];
            l4[j].x += q.x; l4[j].y += q.y; l4[j].z += q.z; l4[j].w += q.w;
        }
    }
    // add scaled noise
    const float4* n4 = reinterpret_cast<const float4*>(noise + t * TE);
    const float4* w4 = reinterpret_cast<const float4*>(nws);
    #pragma unroll
    for (int j = 0; j < 16; j++) {
        float4 n = n4[j], w = w4[j];
        l4[j].x += n.x * w.x; l4[j].y += n.y * w.y;
        l4[j].z += n.z * w.z; l4[j].w += n.w * w.w;
    }
    // top-2 (strict >, ascending scan => lower index wins ties, matches lax.top_k)
    float v1 = -3.402823466e38f, v2 = -3.402823466e38f;
    int i1 = 0, i2 = 0;
    #pragma unroll
    for (int j = 0; j < 16; j++) {
        float vv[4] = { l4[j].x, l4[j].y, l4[j].z, l4[j].w };
        #pragma unroll
        for (int c = 0; c < 4; c++) {
            float v = vv[c]; int e = j * 4 + c;
            if (v > v1)      { v2 = v1; i2 = i1; v1 = v; i1 = e; }
            else if (v > v2) { v2 = v;  i2 = e; }
        }
    }
    float e2 = expf(v2 - v1);
    float sm = 1.0f + e2;
    float w1 = 1.0f / sm;
    float w2 = e2 / sm;

    float4* o4 = reinterpret_cast<float4*>(out + t * TE);
    #pragma unroll
    for (int j = 0; j < 16; j++) {
        float4 o;
        int e = j * 4;
        o.x = (i1 == e    ) ? w1 : (i2 == e    ) ? w2 : 0.0f;
        o.y = (i1 == e + 1) ? w1 : (i2 == e + 1) ? w2 : 0.0f;
        o.z = (i1 == e + 2) ? w1 : (i2 == e + 2) ? w2 : 0.0f;
        o.w = (i1 == e + 3) ? w1 : (i2 == e + 3) ? w2 : 0.0f;
        o4[j] = o;
    }
    if (write_idx) {
        float* oi = out + (size_t)T * TE;
        oi[t * 2 + 0] = (float)i1;
        oi[t * 2 + 1] = (float)i2;
    }
}

extern "C" void kernel_launch(void* const* d_in, const int* in_sizes, int n_in,
                              void* d_out, int out_size) {
    const float* x     = (const float*)d_in[0];
    const float* gw    = (const float*)d_in[1];
    const float* nw    = (const float*)d_in[2];
    const float* noise = (const float*)d_in[3];
    float* out = (float*)d_out;

    int T = in_sizes[0] / TD;                    // 16384 tokens
    int write_idx = (out_size >= T * TE + T * 2) ? 1 : 0;

    gate_gemm<<<dim3(T / BM, SPLIT), 128>>>(x, gw);
    gate_epilogue<<<T / 256, 256>>>(nw, noise, out, T, write_idx);
}

// round 4
// speedup vs baseline: 1.0963x; 1.0963x over previous
#include <cuda_runtime.h>
#include <cuda_bf16.h>
#include <math.h>
#include <stdint.h>

#define TD 1024
#define TE 64
#define BM 64            // tokens per CTA
#define KC 64            // k per chunk
#define NCH (TD / KC)    // 16
#define THREADS 256

// dynamic smem: A terms [3][64][128B] at 0,8192,16384 ; B terms at 24576,+8192,+8192
// epilogue alias: Cs[64][68] f32 at 0 (17408B), scratch w1/w2/i1/i2 at 17408..18431
#define A_T(t) ((t) * 8192)
#define B_T(t) (24576 + (t) * 8192)
#define SMEM_BYTES 49152

// pre-converted W bf16x3 terms, each [64][1024] bf16 = 8192 uint4
__device__ uint4 g_w0[8192], g_w1[8192], g_w2[8192];

typedef unsigned int u32;

__device__ __forceinline__ u32 smem_u32(const void* p) {
    u32 a;
    asm("{ .reg .u64 t; cvta.to.shared.u64 t, %1; cvt.u32.u64 %0, t; }" : "=r"(a) : "l"(p));
    return a;
}
__device__ __forceinline__ u32 pk_bf16x2(float lo, float hi) {
    u32 r;
    asm("cvt.rn.bf16x2.f32 %0, %1, %2;" : "=r"(r) : "f"(hi), "f"(lo));
    return r;
}
// 2 floats -> 3 packed bf16x2 terms (hi, mid, lo)
__device__ __forceinline__ void split3(float vl, float vh, u32& t0, u32& t1, u32& t2) {
    t0 = pk_bf16x2(vl, vh);
    float f0l = __uint_as_float(t0 << 16);
    float f0h = __uint_as_float(t0 & 0xFFFF0000u);
    float r1l = vl - f0l, r1h = vh - f0h;
    t1 = pk_bf16x2(r1l, r1h);
    float f1l = __uint_as_float(t1 << 16);
    float f1h = __uint_as_float(t1 & 0xFFFF0000u);
    t2 = pk_bf16x2(r1l - f1l, r1h - f1h);
}
__device__ __forceinline__ void ldsm4(u32 a, u32& r0, u32& r1, u32& r2, u32& r3) {
    asm volatile("ldmatrix.sync.aligned.m8n8.x4.shared.b16 {%0,%1,%2,%3}, [%4];"
                 : "=r"(r0), "=r"(r1), "=r"(r2), "=r"(r3) : "r"(a));
}
__device__ __forceinline__ void mma16816(float* c, const u32* A, u32 b0, u32 b1) {
    asm volatile(
        "mma.sync.aligned.m16n8k16.row.col.f32.bf16.bf16.f32 "
        "{%0,%1,%2,%3}, {%4,%5,%6,%7}, {%8,%9}, {%0,%1,%2,%3};"
        : "+f"(c[0]), "+f"(c[1]), "+f"(c[2]), "+f"(c[3])
        : "r"(A[0]), "r"(A[1]), "r"(A[2]), "r"(A[3]), "r"(b0), "r"(b1));
}
// swizzled byte offset inside a [64][128B] tile: row*128 + (cb ^ ((row&7)<<4))
__device__ __forceinline__ u32 swz(int row, u32 cb) {
    return (u32)(row * 128) + (cb ^ (u32)((row & 7) << 4));
}

// ---------------- pre-kernel: W fp32 -> 3 bf16 terms ----------------
__global__ void __launch_bounds__(256) wconv_kernel(const float* __restrict__ gw) {
    int i = blockIdx.x * 256 + threadIdx.x;     // 0..8191
    const float4* p = reinterpret_cast<const float4*>(gw) + i * 2;
    float4 a = p[0], b = p[1];
    uint4 u0, u1, u2;
    split3(a.x, a.y, u0.x, u1.x, u2.x);
    split3(a.z, a.w, u0.y, u1.y, u2.y);
    split3(b.x, b.y, u0.z, u1.z, u2.z);
    split3(b.z, b.w, u0.w, u1.w, u2.w);
    g_w0[i] = u0; g_w1[i] = u1; g_w2[i] = u2;
}

// ---------------- main fused kernel ----------------
__global__ void __launch_bounds__(THREADS, 2) gate_kernel(
    const float* __restrict__ x,      // [T, 1024]
    const float* __restrict__ nw,     // [64]
    const float* __restrict__ noise,  // [T, 64]
    float* __restrict__ out,
    int T, int write_idx)
{
    extern __shared__ char smem[];
    const u32 sb = smem_u32(smem);
    const int tid  = threadIdx.x;
    const int lane = tid & 31;
    const int wid  = tid >> 5;
    const int mt = wid & 3;            // token tile: rows mt*16..+15
    const int nh = wid >> 2;           // expert half: nh*32..+31
    const long long t0 = (long long)blockIdx.x * BM;

    // loader roles
    const int srow = tid >> 2;         // 0..63
    const int sq   = tid & 3;          // quarter of k-chunk (16 elems)

    // lane-constant fragment address components
    const int a_row = mt * 16 + (lane & 15);
    const u32 a_off0 = (u32)(a_row * 128);
    const u32 a_msk  = (u32)((a_row & 7) << 4);
    const u32 a_half = (u32)((lane >> 4) << 4);
    const int b_row = nh * 32 + lane;
    const u32 b_off0 = (u32)(b_row * 128);
    const u32 b_msk  = (u32)((b_row & 7) << 4);

    float acc[4][4];
    #pragma unroll
    for (int i = 0; i < 4; i++)
        #pragma unroll
        for (int j = 0; j < 4; j++) acc[i][j] = 0.0f;

    // prefetch chunk 0
    float4 xr[4];
    uint4 wv[3][2];
    {
        const float* xp = x + (t0 + srow) * TD + sq * 16;
        #pragma unroll
        for (int g = 0; g < 4; g++) xr[g] = *reinterpret_cast<const float4*>(xp + g * 4);
        int wi = srow * 128 + sq * 2;
        wv[0][0] = g_w0[wi]; wv[0][1] = g_w0[wi + 1];
        wv[1][0] = g_w1[wi]; wv[1][1] = g_w1[wi + 1];
        wv[2][0] = g_w2[wi]; wv[2][1] = g_w2[wi + 1];
    }

    const int PA[6] = {0, 0, 1, 1, 0, 2};
    const int PB[6] = {0, 1, 0, 1, 2, 0};

    for (int c = 0; c < NCH; c++) {
        __syncthreads();   // all warps done reading previous chunk
        // --- store X terms (fp32 -> bf16x3) swizzled ---
        #pragma unroll
        for (int g2 = 0; g2 < 2; g2++) {
            float4 a = xr[2 * g2], b = xr[2 * g2 + 1];
            uint4 u0, u1, u2;
            split3(a.x, a.y, u0.x, u1.x, u2.x);
            split3(a.z, a.w, u0.y, u1.y, u2.y);
            split3(b.x, b.y, u0.z, u1.z, u2.z);
            split3(b.z, b.w, u0.w, u1.w, u2.w);
            u32 off = swz(srow, (u32)(sq * 32 + g2 * 16));
            *reinterpret_cast<uint4*>(smem + A_T(0) + off) = u0;
            *reinterpret_cast<uint4*>(smem + A_T(1) + off) = u1;
            *reinterpret_cast<uint4*>(smem + A_T(2) + off) = u2;
            *reinterpret_cast<uint4*>(smem + B_T(0) + off) = wv[0][g2];
            *reinterpret_cast<uint4*>(smem + B_T(1) + off) = wv[1][g2];
            *reinterpret_cast<uint4*>(smem + B_T(2) + off) = wv[2][g2];
        }
        __syncthreads();
        // --- prefetch chunk c+1 ---
        if (c + 1 < NCH) {
            int kb = (c + 1) * KC;
            const float* xp = x + (t0 + srow) * TD + kb + sq * 16;
            #pragma unroll
            for (int g = 0; g < 4; g++) xr[g] = *reinterpret_cast<const float4*>(xp + g * 4);
            int wi = srow * 128 + (kb >> 3) + sq * 2;
            wv[0][0] = g_w0[wi]; wv[0][1] = g_w0[wi + 1];
            wv[1][0] = g_w1[wi]; wv[1][1] = g_w1[wi + 1];
            wv[2][0] = g_w2[wi]; wv[2][1] = g_w2[wi + 1];
        }
        // --- compute: 4 k16-steps x (3 A-frags, 6 B-frags, 24 HMMA) ---
        #pragma unroll
        for (int ks = 0; ks < 4; ks++) {
            u32 aF[3][4], bF[3][8];
            u32 cbA = ((u32)(ks * 32) + a_half) ^ a_msk;
            u32 cb0 = ((u32)(ks * 32)) ^ b_msk;
            u32 cb1 = ((u32)(ks * 32 + 16)) ^ b_msk;
            #pragma unroll
            for (int t = 0; t < 3; t++) {
                ldsm4(sb + A_T(t) + a_off0 + cbA, aF[t][0], aF[t][1], aF[t][2], aF[t][3]);
                ldsm4(sb + B_T(t) + b_off0 + cb0, bF[t][0], bF[t][1], bF[t][2], bF[t][3]);
                ldsm4(sb + B_T(t) + b_off0 + cb1, bF[t][4], bF[t][5], bF[t][6], bF[t][7]);
            }
            #pragma unroll
            for (int p = 0; p < 6; p++)
                #pragma unroll
                for (int nt = 0; nt < 4; nt++)
                    mma16816(acc[nt], aF[PA[p]], bF[PB[p]][nt], bF[PB[p]][4 + nt]);
        }
    }

    // ---------------- epilogue ----------------
    __syncthreads();   // done with A/B smem; alias as Cs
    float* Cs  = reinterpret_cast<float*>(smem);            // [64][68]
    float* w1s = reinterpret_cast<float*>(smem + 17408);
    float* w2s = reinterpret_cast<float*>(smem + 17664);
    int*   i1s = reinterpret_cast<int*>(smem + 17920);
    int*   i2s = reinterpret_cast<int*>(smem + 18176);

    {
        int g  = lane >> 2, tq = lane & 3;
        int r0 = mt * 16 + g;
        #pragma unroll
        for (int nt = 0; nt < 4; nt++) {
            int col = nh * 32 + nt * 8 + 2 * tq;
            *reinterpret_cast<float2*>(&Cs[r0 * 68 + col])       = make_float2(acc[nt][0], acc[nt][1]);
            *reinterpret_cast<float2*>(&Cs[(r0 + 8) * 68 + col]) = make_float2(acc[nt][2], acc[nt][3]);
        }
    }
    __syncthreads();

    if (tid < BM) {
        long long t = t0 + tid;
        const float* nr = noise + t * TE;
        const float* rowp = Cs + tid * 68;
        float v1 = -3.402823466e38f, v2 = -3.402823466e38f;
        int i1 = 0, i2 = 0;
        #pragma unroll
        for (int e = 0; e < TE; e++) {
            float v = rowp[e] + nr[e] * __ldg(nw + e);
            if (v > v1)      { v2 = v1; i2 = i1; v1 = v; i1 = e; }
            else if (v > v2) { v2 = v;  i2 = e; }
        }
        float e2 = expf(v2 - v1);
        float sm = 1.0f + e2;
        w1s[tid] = 1.0f / sm;
        w2s[tid] = e2 / sm;
        i1s[tid] = i1;
        i2s[tid] = i2;
    }
    __syncthreads();

    // coalesced weight scatter: 64*64 floats = 1024 float4
    float4* o4 = reinterpret_cast<float4*>(out + t0 * TE);
    #pragma unroll
    for (int u = 0; u < 4; u++) {
        int idx = u * 256 + tid;
        int m  = idx >> 4;
        int e0 = (idx & 15) << 2;
        int i1 = i1s[m], i2 = i2s[m];
        float w1 = w1s[m], w2 = w2s[m];
        float4 o;
        o.x = (i1 == e0    ) ? w1 : (i2 == e0    ) ? w2 : 0.0f;
        o.y = (i1 == e0 + 1) ? w1 : (i2 == e0 + 1) ? w2 : 0.0f;
        o.z = (i1 == e0 + 2) ? w1 : (i2 == e0 + 2) ? w2 : 0.0f;
        o.w = (i1 == e0 + 3) ? w1 : (i2 == e0 + 3) ? w2 : 0.0f;
        o4[idx] = o;
    }
    if (write_idx && tid < BM) {
        long long t = t0 + tid;
        float* oi = out + (size_t)T * TE;
        oi[t * 2 + 0] = (float)i1s[tid];
        oi[t * 2 + 1] = (float)i2s[tid];
    }
}

extern "C" void kernel_launch(void* const* d_in, const int* in_sizes, int n_in,
                              void* d_out, int out_size) {
    const float* x     = (const float*)d_in[0];
    const float* gw    = (const float*)d_in[1];
    const float* nw    = (const float*)d_in[2];
    const float* noise = (const float*)d_in[3];
    float* out = (float*)d_out;

    int T = in_sizes[0] / TD;                       // 16384
    int write_idx = (out_size >= T * TE + T * 2) ? 1 : 0;

    wconv_kernel<<<32, 256>>>(gw);
    gate_kernel<<<T / BM, THREADS, SMEM_BYTES>>>(x, nw, noise, out, T, write_idx);
}

// round 5
// speedup vs baseline: 1.4996x; 1.3680x over previous
#include <cuda_runtime.h>
#include <cuda_fp16.h>
#include <math.h>
#include <stdint.h>

#define TD 1024
#define TE 64
#define BM 64            // tokens per CTA
#define KC 64            // k per chunk
#define NCH (TD / KC)    // 16
#define THREADS 256

// per-buffer: A terms [2][64 rows][128B] at 0,8192 ; B terms at 16384,24576 => 32KB
// two buffers: 0 and 32768.  Epilogue alias: Cs[64][68] f32 (17408B) + scratch.
#define BUF_SZ 32768
#define A_T(t) ((t) * 8192)
#define B_T(t) (16384 + (t) * 8192)
#define SMEM_BYTES 65536

// pre-converted W fp16x2 terms, each [64][1024] fp16 => [64][128] uint4
__device__ uint4 g_w0[8192], g_w1[8192];

typedef unsigned int u32;

__device__ __forceinline__ u32 smem_u32(const void* p) {
    u32 a;
    asm("{ .reg .u64 t; cvta.to.shared.u64 t, %1; cvt.u32.u64 %0, t; }" : "=r"(a) : "l"(p));
    return a;
}
// 2 floats -> 2 packed fp16x2 terms (hi, residual-lo)
__device__ __forceinline__ void split2(float vl, float vh, u32& t0, u32& t1) {
    __half2 h0 = __floats2half2_rn(vl, vh);
    float2 f0 = __half22float2(h0);
    __half2 h1 = __floats2half2_rn(vl - f0.x, vh - f0.y);
    t0 = *reinterpret_cast<u32*>(&h0);
    t1 = *reinterpret_cast<u32*>(&h1);
}
__device__ __forceinline__ void ldsm4(u32 a, u32& r0, u32& r1, u32& r2, u32& r3) {
    asm volatile("ldmatrix.sync.aligned.m8n8.x4.shared.b16 {%0,%1,%2,%3}, [%4];"
                 : "=r"(r0), "=r"(r1), "=r"(r2), "=r"(r3) : "r"(a));
}
__device__ __forceinline__ void mma16816(float* c, const u32* A, u32 b0, u32 b1) {
    asm volatile(
        "mma.sync.aligned.m16n8k16.row.col.f32.f16.f16.f32 "
        "{%0,%1,%2,%3}, {%4,%5,%6,%7}, {%8,%9}, {%0,%1,%2,%3};"
        : "+f"(c[0]), "+f"(c[1]), "+f"(c[2]), "+f"(c[3])
        : "r"(A[0]), "r"(A[1]), "r"(A[2]), "r"(A[3]), "r"(b0), "r"(b1));
}
// swizzled byte offset inside a [64][128B] tile
__device__ __forceinline__ u32 swz(int row, u32 cb) {
    return (u32)(row * 128) + (cb ^ (u32)((row & 7) << 4));
}

// ---------------- pre-kernel: W fp32 -> 2 fp16 terms ----------------
__global__ void __launch_bounds__(256) wconv_kernel(const float* __restrict__ gw) {
    int i = blockIdx.x * 256 + threadIdx.x;     // 0..8191, 8 floats each
    const float4* p = reinterpret_cast<const float4*>(gw) + i * 2;
    float4 a = p[0], b = p[1];
    uint4 u0, u1;
    split2(a.x, a.y, u0.x, u1.x);
    split2(a.z, a.w, u0.y, u1.y);
    split2(b.x, b.y, u0.z, u1.z);
    split2(b.z, b.w, u0.w, u1.w);
    g_w0[i] = u0; g_w1[i] = u1;
}

// ---------------- main fused kernel ----------------
__global__ void __launch_bounds__(THREADS, 2) gate_kernel(
    const float* __restrict__ x,      // [T, 1024]
    const float* __restrict__ nw,     // [64]
    const float* __restrict__ noise,  // [T, 64]
    float* __restrict__ out,
    int T, int write_idx)
{
    extern __shared__ char smem[];
    const u32 sb = smem_u32(smem);
    const int tid  = threadIdx.x;
    const int lane = tid & 31;
    const int wid  = tid >> 5;
    const int mt = wid & 3;            // token tile: rows mt*16..+15
    const int nh = wid >> 2;           // expert half: nh*32..+31
    const long long t0 = (long long)blockIdx.x * BM;

    // loader roles: srow 0..63, sq = quarter of k-chunk (16 elems)
    const int srow = tid >> 2;
    const int sq   = tid & 3;

    // lane-constant fragment address components
    const int a_row = mt * 16 + (lane & 15);
    const u32 a_off0 = (u32)(a_row * 128);
    const u32 a_msk  = (u32)((a_row & 7) << 4);
    const u32 a_half = (u32)((lane >> 4) << 4);
    const int b_row = nh * 32 + lane;
    const u32 b_off0 = (u32)(b_row * 128);
    const u32 b_msk  = (u32)((b_row & 7) << 4);

    float acc[4][4];
    #pragma unroll
    for (int i = 0; i < 4; i++)
        #pragma unroll
        for (int j = 0; j < 4; j++) acc[i][j] = 0.0f;

    float4 xr[4];
    uint4 wv[2][2];

    // prefetch chunk 0 (LDG -> regs)
    {
        const float* xp = x + (t0 + srow) * TD + sq * 16;
        #pragma unroll
        for (int g = 0; g < 4; g++) xr[g] = *reinterpret_cast<const float4*>(xp + g * 4);
        int wi = srow * 128 + sq * 2;
        wv[0][0] = g_w0[wi]; wv[0][1] = g_w0[wi + 1];
        wv[1][0] = g_w1[wi]; wv[1][1] = g_w1[wi + 1];
    }
    // store chunk 0 into buffer 0
    #pragma unroll
    for (int g2 = 0; g2 < 2; g2++) {
        float4 a = xr[2 * g2], b = xr[2 * g2 + 1];
        uint4 u0, u1;
        split2(a.x, a.y, u0.x, u1.x);
        split2(a.z, a.w, u0.y, u1.y);
        split2(b.x, b.y, u0.z, u1.z);
        split2(b.z, b.w, u0.w, u1.w);
        u32 off = swz(srow, (u32)(sq * 32 + g2 * 16));
        *reinterpret_cast<uint4*>(smem + A_T(0) + off) = u0;
        *reinterpret_cast<uint4*>(smem + A_T(1) + off) = u1;
        *reinterpret_cast<uint4*>(smem + B_T(0) + off) = wv[0][g2];
        *reinterpret_cast<uint4*>(smem + B_T(1) + off) = wv[1][g2];
    }
    __syncthreads();

    const int PA[3] = {0, 0, 1};
    const int PB[3] = {0, 1, 0};

    for (int c = 0; c < NCH; c++) {
        const u32 bufo = (u32)((c & 1) * BUF_SZ);
        // --- prefetch chunk c+1 (LDG; consumed after compute) ---
        if (c + 1 < NCH) {
            int kb = (c + 1) * KC;
            const float* xp = x + (t0 + srow) * TD + kb + sq * 16;
            #pragma unroll
            for (int g = 0; g < 4; g++) xr[g] = *reinterpret_cast<const float4*>(xp + g * 4);
            int wi = srow * 128 + (kb >> 3) + sq * 2;
            wv[0][0] = g_w0[wi]; wv[0][1] = g_w0[wi + 1];
            wv[1][0] = g_w1[wi]; wv[1][1] = g_w1[wi + 1];
        }
        // --- compute chunk c: 4 k16-steps x (2 A-frags, 4 B-frags, 12 HMMA) ---
        #pragma unroll
        for (int ks = 0; ks < 4; ks++) {
            u32 aF[2][4], bF[2][8];
            u32 cbA = ((u32)(ks * 32) + a_half) ^ a_msk;
            u32 cb0 = ((u32)(ks * 32)) ^ b_msk;
            u32 cb1 = ((u32)(ks * 32 + 16)) ^ b_msk;
            #pragma unroll
            for (int t = 0; t < 2; t++) {
                ldsm4(sb + bufo + A_T(t) + a_off0 + cbA, aF[t][0], aF[t][1], aF[t][2], aF[t][3]);
                ldsm4(sb + bufo + B_T(t) + b_off0 + cb0, bF[t][0], bF[t][1], bF[t][2], bF[t][3]);
                ldsm4(sb + bufo + B_T(t) + b_off0 + cb1, bF[t][4], bF[t][5], bF[t][6], bF[t][7]);
            }
            #pragma unroll
            for (int p = 0; p < 3; p++)
                #pragma unroll
                for (int nt = 0; nt < 4; nt++)
                    mma16816(acc[nt], aF[PA[p]], bF[PB[p]][nt], bF[PB[p]][4 + nt]);
        }
        // --- convert + store chunk c+1 into other buffer (overlaps peers' MMA) ---
        if (c + 1 < NCH) {
            char* bp = smem + ((c + 1) & 1) * BUF_SZ;
            #pragma unroll
            for (int g2 = 0; g2 < 2; g2++) {
                float4 a = xr[2 * g2], b = xr[2 * g2 + 1];
                uint4 u0, u1;
                split2(a.x, a.y, u0.x, u1.x);
                split2(a.z, a.w, u0.y, u1.y);
                split2(b.x, b.y, u0.z, u1.z);
                split2(b.z, b.w, u0.w, u1.w);
                u32 off = swz(srow, (u32)(sq * 32 + g2 * 16));
                *reinterpret_cast<uint4*>(bp + A_T(0) + off) = u0;
                *reinterpret_cast<uint4*>(bp + A_T(1) + off) = u1;
                *reinterpret_cast<uint4*>(bp + B_T(0) + off) = wv[0][g2];
                *reinterpret_cast<uint4*>(bp + B_T(1) + off) = wv[1][g2];
            }
        }
        __syncthreads();
    }

    // ---------------- epilogue ----------------
    float* Cs  = reinterpret_cast<float*>(smem);            // [64][68]
    float* w1s = reinterpret_cast<float*>(smem + 17408);
    float* w2s = reinterpret_cast<float*>(smem + 17664);
    int*   i1s = reinterpret_cast<int*>(smem + 17920);
    int*   i2s = reinterpret_cast<int*>(smem + 18176);

    {
        int g  = lane >> 2, tq = lane & 3;
        int r0 = mt * 16 + g;
        #pragma unroll
        for (int nt = 0; nt < 4; nt++) {
            int col = nh * 32 + nt * 8 + 2 * tq;
            *reinterpret_cast<float2*>(&Cs[r0 * 68 + col])       = make_float2(acc[nt][0], acc[nt][1]);
            *reinterpret_cast<float2*>(&Cs[(r0 + 8) * 68 + col]) = make_float2(acc[nt][2], acc[nt][3]);
        }
    }
    __syncthreads();

    if (tid < BM) {
        long long t = t0 + tid;
        const float* nr = noise + t * TE;
        const float* rowp = Cs + tid * 68;
        float v1 = -3.402823466e38f, v2 = -3.402823466e38f;
        int i1 = 0, i2 = 0;
        #pragma unroll
        for (int e = 0; e < TE; e++) {
            float v = rowp[e] + nr[e] * __ldg(nw + e);
            if (v > v1)      { v2 = v1; i2 = i1; v1 = v; i1 = e; }
            else if (v > v2) { v2 = v;  i2 = e; }
        }
        float e2 = expf(v2 - v1);
        float sm = 1.0f + e2;
        w1s[tid] = 1.0f / sm;
        w2s[tid] = e2 / sm;
        i1s[tid] = i1;
        i2s[tid] = i2;
    }
    __syncthreads();

    // coalesced weight scatter: 64*64 floats = 1024 float4
    float4* o4 = reinterpret_cast<float4*>(out + t0 * TE);
    #pragma unroll
    for (int u = 0; u < 4; u++) {
        int idx = u * 256 + tid;
        int m  = idx >> 4;
        int e0 = (idx & 15) << 2;
        int i1 = i1s[m], i2 = i2s[m];
        float w1 = w1s[m], w2 = w2s[m];
        float4 o;
        o.x = (i1 == e0    ) ? w1 : (i2 == e0    ) ? w2 : 0.0f;
        o.y = (i1 == e0 + 1) ? w1 : (i2 == e0 + 1) ? w2 : 0.0f;
        o.z = (i1 == e0 + 2) ? w1 : (i2 == e0 + 2) ? w2 : 0.0f;
        o.w = (i1 == e0 + 3) ? w1 : (i2 == e0 + 3) ? w2 : 0.0f;
        o4[idx] = o;
    }
    if (write_idx && tid < BM) {
        long long t = t0 + tid;
        float* oi = out + (size_t)T * TE;
        oi[t * 2 + 0] = (float)i1s[tid];
        oi[t * 2 + 1] = (float)i2s[tid];
    }
}

extern "C" void kernel_launch(void* const* d_in, const int* in_sizes, int n_in,
                              void* d_out, int out_size) {
    const float* x     = (const float*)d_in[0];
    const float* gw    = (const float*)d_in[1];
    const float* nw    = (const float*)d_in[2];
    const float* noise = (const float*)d_in[3];
    float* out = (float*)d_out;

    int T = in_sizes[0] / TD;                       // 16384
    int write_idx = (out_size >= T * TE + T * 2) ? 1 : 0;

    static int smem_set = 0;
    if (!smem_set) {
        cudaFuncSetAttribute(gate_kernel, cudaFuncAttributeMaxDynamicSharedMemorySize, SMEM_BYTES);
        smem_set = 1;
    }

    wconv_kernel<<<32, 256>>>(gw);
    gate_kernel<<<T / BM, THREADS, SMEM_BYTES>>>(x, nw, noise, out, T, write_idx);
}

// round 6
// speedup vs baseline: 1.7551x; 1.1704x over previous
#include <cuda_runtime.h>
#include <cuda_fp16.h>
#include <math.h>
#include <stdint.h>

#define TD 1024
#define TE 64
#define BM 64            // tokens per CTA
#define NKS 64           // k16 steps
#define THREADS 256

// smem layout (epilogue only):
//   Cs [64][66] f32            : 0 .. 16896
//   w1s/w2s/i1s/i2s (64 each)  : 16896 .. 17920
//   noiseS [64][64] f32        : 17920 .. 34304
//   nws [64] f32               : 34304 .. 34560
#define CS_OFF    0
#define CS_STRIDE 66
#define W1_OFF    16896
#define W2_OFF    17152
#define I1_OFF    17408
#define I2_OFF    17664
#define NZ_OFF    17920
#define NW_OFF    34304
#define SMEM_BYTES 34560

typedef unsigned int u32;

// W in fragment order: [kstep][term][n8tile][lane] -> uint2{b0,b1}; 64*2*8*32 = 32768
__device__ uint2 g_wfrag[32768];

// 2 floats -> 2 packed fp16x2 terms (hi, residual-lo)
__device__ __forceinline__ void split2(float vl, float vh, u32& t0, u32& t1) {
    __half2 h0 = __floats2half2_rn(vl, vh);
    float2 f0 = __half22float2(h0);
    __half2 h1 = __floats2half2_rn(vl - f0.x, vh - f0.y);
    t0 = *reinterpret_cast<u32*>(&h0);
    t1 = *reinterpret_cast<u32*>(&h1);
}
__device__ __forceinline__ void mma16816(float* c, const u32* A, u32 b0, u32 b1) {
    asm volatile(
        "mma.sync.aligned.m16n8k16.row.col.f32.f16.f16.f32 "
        "{%0,%1,%2,%3}, {%4,%5,%6,%7}, {%8,%9}, {%0,%1,%2,%3};"
        : "+f"(c[0]), "+f"(c[1]), "+f"(c[2]), "+f"(c[3])
        : "r"(A[0]), "r"(A[1]), "r"(A[2]), "r"(A[3]), "r"(b0), "r"(b1));
}

// ---------------- pre-kernel: W fp32 -> fp16x2 fragments ----------------
// thread id -> (kstep, n8tile, lane); handles both terms and b0/b1.
__global__ void __launch_bounds__(256) wconv_kernel(const float* __restrict__ gw) {
    int t = blockIdx.x * 256 + threadIdx.x;     // 0..16383
    int ks   = t >> 8;                          // /256
    int nt   = (t >> 5) & 7;
    int lane = t & 31;
    int n  = nt * 8 + (lane >> 2);
    int k0 = ks * 16 + 2 * (lane & 3);
    const float* wp = gw + n * TD + k0;
    float2 p0 = *reinterpret_cast<const float2*>(wp);       // k0, k0+1
    float2 p1 = *reinterpret_cast<const float2*>(wp + 8);   // k0+8, k0+9
    u32 b0t0, b0t1, b1t0, b1t1;
    split2(p0.x, p0.y, b0t0, b0t1);
    split2(p1.x, p1.y, b1t0, b1t1);
    int base = ks * 512 + nt * 32 + lane;
    g_wfrag[base]       = make_uint2(b0t0, b1t0);   // term 0
    g_wfrag[base + 256] = make_uint2(b0t1, b1t1);   // term 1
}

// ---------------- main fused kernel ----------------
__global__ void __launch_bounds__(THREADS, 2) gate_kernel(
    const float* __restrict__ x,      // [T, 1024]
    const float* __restrict__ nw,     // [64]
    const float* __restrict__ noise,  // [T, 64]
    float* __restrict__ out,
    int T, int write_idx)
{
    extern __shared__ char smem[];
    const int tid  = threadIdx.x;
    const int lane = tid & 31;
    const int wid  = tid >> 5;
    const int mt = wid & 3;            // token tile: rows mt*16..+15
    const int nh = wid >> 2;           // expert half: nh*32..+31
    const long long t0 = (long long)blockIdx.x * BM;

    // --- prefetch noise + nw into smem (hides epilogue tail) ---
    {
        const float4* np = reinterpret_cast<const float4*>(noise + t0 * TE);
        float4* ns = reinterpret_cast<float4*>(smem + NZ_OFF);
        #pragma unroll
        for (int u = 0; u < 4; u++) ns[u * 256 + tid] = np[u * 256 + tid];
        if (tid < TE) reinterpret_cast<float*>(smem + NW_OFF)[tid] = nw[tid];
    }

    // A source pointer: lane covers rows (mt*16 + lane/4) and +8, k pairs at 2*(lane&3), +8
    const float* xA = x + (t0 + mt * 16 + (lane >> 2)) * TD + 2 * (lane & 3);
    // B fragment pointer for this warp's n-half
    const uint2* bp = g_wfrag + (nh * 4) * 32 + lane;

    float acc[4][4];
    #pragma unroll
    for (int i = 0; i < 4; i++)
        #pragma unroll
        for (int j = 0; j < 4; j++) acc[i][j] = 0.0f;

    // software pipeline registers
    float2 ar[4];
    uint2  br[2][4];

    // load k-step 0
    ar[0] = *reinterpret_cast<const float2*>(xA);
    ar[1] = *reinterpret_cast<const float2*>(xA + 8);
    ar[2] = *reinterpret_cast<const float2*>(xA + 8 * TD);
    ar[3] = *reinterpret_cast<const float2*>(xA + 8 * TD + 8);
    #pragma unroll
    for (int t = 0; t < 2; t++)
        #pragma unroll
        for (int j = 0; j < 4; j++) br[t][j] = bp[t * 256 + j * 32];

    #pragma unroll 4
    for (int ks = 0; ks < NKS; ks++) {
        // prefetch k-step ks+1 (wraps to 0 on last iter; harmless in-range load)
        const int nks = (ks + 1) & (NKS - 1);
        float2 an[4];
        uint2  bn[2][4];
        {
            const float* xp = xA + nks * 16;
            an[0] = *reinterpret_cast<const float2*>(xp);
            an[1] = *reinterpret_cast<const float2*>(xp + 8);
            an[2] = *reinterpret_cast<const float2*>(xp + 8 * TD);
            an[3] = *reinterpret_cast<const float2*>(xp + 8 * TD + 8);
            const uint2* bq = bp + nks * 512;
            #pragma unroll
            for (int t = 0; t < 2; t++)
                #pragma unroll
                for (int j = 0; j < 4; j++) bn[t][j] = bq[t * 256 + j * 32];
        }
        // convert current A to fp16x2 fragments (both terms)
        u32 aF[2][4];
        split2(ar[0].x, ar[0].y, aF[0][0], aF[1][0]);   // a0 = (r0, k0)
        split2(ar[2].x, ar[2].y, aF[0][1], aF[1][1]);   // a1 = (r1, k0)
        split2(ar[1].x, ar[1].y, aF[0][2], aF[1][2]);   // a2 = (r0, k0+8)
        split2(ar[3].x, ar[3].y, aF[0][3], aF[1][3]);   // a3 = (r1, k0+8)
        // 3 term-pairs x 4 n-tiles = 12 HMMA
        #pragma unroll
        for (int nt = 0; nt < 4; nt++) mma16816(acc[nt], aF[0], br[0][nt].x, br[0][nt].y);
        #pragma unroll
        for (int nt = 0; nt < 4; nt++) mma16816(acc[nt], aF[0], br[1][nt].x, br[1][nt].y);
        #pragma unroll
        for (int nt = 0; nt < 4; nt++) mma16816(acc[nt], aF[1], br[0][nt].x, br[0][nt].y);
        // rotate
        #pragma unroll
        for (int i = 0; i < 4; i++) ar[i] = an[i];
        #pragma unroll
        for (int t = 0; t < 2; t++)
            #pragma unroll
            for (int j = 0; j < 4; j++) br[t][j] = bn[t][j];
    }

    // ---------------- epilogue ----------------
    float* Cs  = reinterpret_cast<float*>(smem + CS_OFF);
    float* w1s = reinterpret_cast<float*>(smem + W1_OFF);
    float* w2s = reinterpret_cast<float*>(smem + W2_OFF);
    int*   i1s = reinterpret_cast<int*>(smem + I1_OFF);
    int*   i2s = reinterpret_cast<int*>(smem + I2_OFF);
    const float* nzS  = reinterpret_cast<const float*>(smem + NZ_OFF);
    const float* nwsS = reinterpret_cast<const float*>(smem + NW_OFF);

    {
        int g  = lane >> 2, tq = lane & 3;
        int r0 = mt * 16 + g;
        #pragma unroll
        for (int nt = 0; nt < 4; nt++) {
            int col = nh * 32 + nt * 8 + 2 * tq;
            *reinterpret_cast<float2*>(&Cs[r0 * CS_STRIDE + col])       = make_float2(acc[nt][0], acc[nt][1]);
            *reinterpret_cast<float2*>(&Cs[(r0 + 8) * CS_STRIDE + col]) = make_float2(acc[nt][2], acc[nt][3]);
        }
    }
    __syncthreads();

    if (tid < BM) {
        const float* rowp = Cs + tid * CS_STRIDE;
        const float* nr   = nzS + tid * TE;
        float v1 = -3.402823466e38f, v2 = -3.402823466e38f;
        int i1 = 0, i2 = 0;
        #pragma unroll
        for (int e = 0; e < TE; e++) {
            float v = rowp[e] + nr[e] * nwsS[e];
            if (v > v1)      { v2 = v1; i2 = i1; v1 = v; i1 = e; }
            else if (v > v2) { v2 = v;  i2 = e; }
        }
        float e2 = expf(v2 - v1);
        float sm = 1.0f + e2;
        w1s[tid] = 1.0f / sm;
        w2s[tid] = e2 / sm;
        i1s[tid] = i1;
        i2s[tid] = i2;
    }
    __syncthreads();

    // coalesced weight scatter: 64*64 floats = 1024 float4
    float4* o4 = reinterpret_cast<float4*>(out + t0 * TE);
    #pragma unroll
    for (int u = 0; u < 4; u++) {
        int idx = u * 256 + tid;
        int m  = idx >> 4;
        int e0 = (idx & 15) << 2;
        int i1 = i1s[m], i2 = i2s[m];
        float w1 = w1s[m], w2 = w2s[m];
        float4 o;
        o.x = (i1 == e0    ) ? w1 : (i2 == e0    ) ? w2 : 0.0f;
        o.y = (i1 == e0 + 1) ? w1 : (i2 == e0 + 1) ? w2 : 0.0f;
        o.z = (i1 == e0 + 2) ? w1 : (i2 == e0 + 2) ? w2 : 0.0f;
        o.w = (i1 == e0 + 3) ? w1 : (i2 == e0 + 3) ? w2 : 0.0f;
        o4[idx] = o;
    }
    if (write_idx && tid < BM) {
        long long t = t0 + tid;
        float* oi = out + (size_t)T * TE;
        oi[t * 2 + 0] = (float)i1s[tid];
        oi[t * 2 + 1] = (float)i2s[tid];
    }
}

extern "C" void kernel_launch(void* const* d_in, const int* in_sizes, int n_in,
                              void* d_out, int out_size) {
    const float* x     = (const float*)d_in[0];
    const float* gw    = (const float*)d_in[1];
    const float* nw    = (const float*)d_in[2];
    const float* noise = (const float*)d_in[3];
    float* out = (float*)d_out;

    int T = in_sizes[0] / TD;                       // 16384
    int write_idx = (out_size >= T * TE + T * 2) ? 1 : 0;

    wconv_kernel<<<64, 256>>>(gw);
    gate_kernel<<<T / BM, THREADS, SMEM_BYTES>>>(x, nw, noise, out, T, write_idx);
}

// round 7
// speedup vs baseline: 2.1310x; 1.2141x over previous
#include <cuda_runtime.h>
#include <cuda_fp16.h>
#include <math.h>
#include <stdint.h>

#define TD 1024
#define TE 64
#define BM 128           // tokens per CTA (grid = 128)
#define NKS 64           // k16 steps
#define THREADS 256

// smem layout (epilogue + staged noise):
//   Cs [128][66] f32           : 0 .. 33792
//   w1s/w2s/i1s/i2s (128 each) : 33792 .. 35840
//   noiseS [128][64] f32       : 35840 .. 68608
//   nws [64] f32               : 68608 .. 68864
#define CS_OFF    0
#define CS_STRIDE 66
#define W1_OFF    33792
#define W2_OFF    34304
#define I1_OFF    34816
#define I2_OFF    35328
#define NZ_OFF    35840
#define NW_OFF    68608
#define SMEM_BYTES 68864

typedef unsigned int u32;

// W in fragment order: [kstep][term][n8tile][lane] -> uint2{b0,b1}; 64*2*8*32 = 32768
__device__ uint2 g_wfrag[32768];

// 2 floats -> 2 packed fp16x2 terms (hi, residual-lo)
__device__ __forceinline__ void split2(float vl, float vh, u32& t0, u32& t1) {
    __half2 h0 = __floats2half2_rn(vl, vh);
    float2 f0 = __half22float2(h0);
    __half2 h1 = __floats2half2_rn(vl - f0.x, vh - f0.y);
    t0 = *reinterpret_cast<u32*>(&h0);
    t1 = *reinterpret_cast<u32*>(&h1);
}
__device__ __forceinline__ void mma16816(float* c, const u32* A, u32 b0, u32 b1) {
    asm volatile(
        "mma.sync.aligned.m16n8k16.row.col.f32.f16.f16.f32 "
        "{%0,%1,%2,%3}, {%4,%5,%6,%7}, {%8,%9}, {%0,%1,%2,%3};"
        : "+f"(c[0]), "+f"(c[1]), "+f"(c[2]), "+f"(c[3])
        : "r"(A[0]), "r"(A[1]), "r"(A[2]), "r"(A[3]), "r"(b0), "r"(b1));
}

// ---------------- pre-kernel: W fp32 -> fp16x2 fragments ----------------
__global__ void __launch_bounds__(256) wconv_kernel(const float* __restrict__ gw) {
    int t = blockIdx.x * 256 + threadIdx.x;     // 0..16383
    int ks   = t >> 8;
    int nt   = (t >> 5) & 7;
    int lane = t & 31;
    int n  = nt * 8 + (lane >> 2);
    int k0 = ks * 16 + 2 * (lane & 3);
    const float* wp = gw + n * TD + k0;
    float2 p0 = *reinterpret_cast<const float2*>(wp);       // k0, k0+1
    float2 p1 = *reinterpret_cast<const float2*>(wp + 8);   // k0+8, k0+9
    u32 b0t0, b0t1, b1t0, b1t1;
    split2(p0.x, p0.y, b0t0, b0t1);
    split2(p1.x, p1.y, b1t0, b1t1);
    int base = ks * 512 + nt * 32 + lane;
    g_wfrag[base]       = make_uint2(b0t0, b1t0);   // term 0
    g_wfrag[base + 256] = make_uint2(b0t1, b1t1);   // term 1
}

// ---------------- main fused kernel ----------------
__global__ void __launch_bounds__(THREADS, 1) gate_kernel(
    const float* __restrict__ x,      // [T, 1024]
    const float* __restrict__ nw,     // [64]
    const float* __restrict__ noise,  // [T, 64]
    float* __restrict__ out,
    int T, int write_idx)
{
    extern __shared__ char smem[];
    const int tid  = threadIdx.x;
    const int lane = tid & 31;
    const int wid  = tid >> 5;         // warp = 16 tokens x 64 experts
    const long long t0 = (long long)blockIdx.x * BM;

    // --- prefetch noise + nw into smem (hides epilogue tail) ---
    {
        const float4* np = reinterpret_cast<const float4*>(noise + t0 * TE);
        float4* ns = reinterpret_cast<float4*>(smem + NZ_OFF);
        #pragma unroll
        for (int u = 0; u < 8; u++) ns[u * 256 + tid] = np[u * 256 + tid];
        if (tid < TE) reinterpret_cast<float*>(smem + NW_OFF)[tid] = nw[tid];
    }

    // A source: lane covers rows (wid*16 + lane/4) and +8, k pairs at 2*(lane&3), +8
    const float* xA = x + (t0 + wid * 16 + (lane >> 2)) * TD + 2 * (lane & 3);
    // B fragment pointer (full 64 experts per warp)
    const uint2* bp = g_wfrag + lane;

    float acc[8][4];
    #pragma unroll
    for (int i = 0; i < 8; i++)
        #pragma unroll
        for (int j = 0; j < 4; j++) acc[i][j] = 0.0f;

    // software pipeline registers
    float2 ar[4];
    uint2  br[2][8];

    // load k-step 0
    ar[0] = *reinterpret_cast<const float2*>(xA);
    ar[1] = *reinterpret_cast<const float2*>(xA + 8);
    ar[2] = *reinterpret_cast<const float2*>(xA + 8 * TD);
    ar[3] = *reinterpret_cast<const float2*>(xA + 8 * TD + 8);
    #pragma unroll
    for (int t = 0; t < 2; t++)
        #pragma unroll
        for (int j = 0; j < 8; j++) br[t][j] = bp[t * 256 + j * 32];

    #pragma unroll 2
    for (int ks = 0; ks < NKS; ks++) {
        const int nks = (ks + 1) & (NKS - 1);   // wraps on last iter (harmless)
        float2 an[4];
        uint2  bn[2][8];
        {
            const float* xp = xA + nks * 16;
            an[0] = *reinterpret_cast<const float2*>(xp);
            an[1] = *reinterpret_cast<const float2*>(xp + 8);
            an[2] = *reinterpret_cast<const float2*>(xp + 8 * TD);
            an[3] = *reinterpret_cast<const float2*>(xp + 8 * TD + 8);
            const uint2* bq = bp + nks * 512;
            #pragma unroll
            for (int t = 0; t < 2; t++)
                #pragma unroll
                for (int j = 0; j < 8; j++) bn[t][j] = bq[t * 256 + j * 32];
        }
        // convert current A to fp16x2 fragments (both terms)
        u32 aF[2][4];
        split2(ar[0].x, ar[0].y, aF[0][0], aF[1][0]);
        split2(ar[2].x, ar[2].y, aF[0][1], aF[1][1]);
        split2(ar[1].x, ar[1].y, aF[0][2], aF[1][2]);
        split2(ar[3].x, ar[3].y, aF[0][3], aF[1][3]);
        // 3 term-pairs x 8 n-tiles = 24 HMMA
        #pragma unroll
        for (int nt = 0; nt < 8; nt++) mma16816(acc[nt], aF[0], br[0][nt].x, br[0][nt].y);
        #pragma unroll
        for (int nt = 0; nt < 8; nt++) mma16816(acc[nt], aF[0], br[1][nt].x, br[1][nt].y);
        #pragma unroll
        for (int nt = 0; nt < 8; nt++) mma16816(acc[nt], aF[1], br[0][nt].x, br[0][nt].y);
        // rotate
        #pragma unroll
        for (int i = 0; i < 4; i++) ar[i] = an[i];
        #pragma unroll
        for (int t = 0; t < 2; t++)
            #pragma unroll
            for (int j = 0; j < 8; j++) br[t][j] = bn[t][j];
    }

    // ---------------- epilogue ----------------
    float* Cs  = reinterpret_cast<float*>(smem + CS_OFF);
    float* w1s = reinterpret_cast<float*>(smem + W1_OFF);
    float* w2s = reinterpret_cast<float*>(smem + W2_OFF);
    int*   i1s = reinterpret_cast<int*>(smem + I1_OFF);
    int*   i2s = reinterpret_cast<int*>(smem + I2_OFF);
    const float* nzS  = reinterpret_cast<const float*>(smem + NZ_OFF);
    const float* nwsS = reinterpret_cast<const float*>(smem + NW_OFF);

    {
        int g  = lane >> 2, tq = lane & 3;
        int r0 = wid * 16 + g;
        #pragma unroll
        for (int nt = 0; nt < 8; nt++) {
            int col = nt * 8 + 2 * tq;
            *reinterpret_cast<float2*>(&Cs[r0 * CS_STRIDE + col])       = make_float2(acc[nt][0], acc[nt][1]);
            *reinterpret_cast<float2*>(&Cs[(r0 + 8) * CS_STRIDE + col]) = make_float2(acc[nt][2], acc[nt][3]);
        }
    }
    __syncthreads();

    if (tid < BM) {
        const float* rowp = Cs + tid * CS_STRIDE;
        const float* nr   = nzS + tid * TE;
        float v1 = -3.402823466e38f, v2 = -3.402823466e38f;
        int i1 = 0, i2 = 0;
        #pragma unroll
        for (int e = 0; e < TE; e++) {
            float v = rowp[e] + nr[e] * nwsS[e];
            if (v > v1)      { v2 = v1; i2 = i1; v1 = v; i1 = e; }
            else if (v > v2) { v2 = v;  i2 = e; }
        }
        float e2 = expf(v2 - v1);
        float sm = 1.0f + e2;
        w1s[tid] = 1.0f / sm;
        w2s[tid] = e2 / sm;
        i1s[tid] = i1;
        i2s[tid] = i2;
    }
    __syncthreads();

    // coalesced weight scatter: 128*64 floats = 2048 float4
    float4* o4 = reinterpret_cast<float4*>(out + t0 * TE);
    #pragma unroll
    for (int u = 0; u < 8; u++) {
        int idx = u * 256 + tid;
        int m  = idx >> 4;
        int e0 = (idx & 15) << 2;
        int i1 = i1s[m], i2 = i2s[m];
        float w1 = w1s[m], w2 = w2s[m];
        float4 o;
        o.x = (i1 == e0    ) ? w1 : (i2 == e0    ) ? w2 : 0.0f;
        o.y = (i1 == e0 + 1) ? w1 : (i2 == e0 + 1) ? w2 : 0.0f;
        o.z = (i1 == e0 + 2) ? w1 : (i2 == e0 + 2) ? w2 : 0.0f;
        o.w = (i1 == e0 + 3) ? w1 : (i2 == e0 + 3) ? w2 : 0.0f;
        o4[idx] = o;
    }
    if (write_idx && tid < BM) {
        long long t = t0 + tid;
        float* oi = out + (size_t)T * TE;
        oi[t * 2 + 0] = (float)i1s[tid];
        oi[t * 2 + 1] = (float)i2s[tid];
    }
}

extern "C" void kernel_launch(void* const* d_in, const int* in_sizes, int n_in,
                              void* d_out, int out_size) {
    const float* x     = (const float*)d_in[0];
    const float* gw    = (const float*)d_in[1];
    const float* nw    = (const float*)d_in[2];
    const float* noise = (const float*)d_in[3];
    float* out = (float*)d_out;

    int T = in_sizes[0] / TD;                       // 16384
    int write_idx = (out_size >= T * TE + T * 2) ? 1 : 0;

    cudaFuncSetAttribute(gate_kernel, cudaFuncAttributeMaxDynamicSharedMemorySize, SMEM_BYTES);

    wconv_kernel<<<64, 256>>>(gw);
    gate_kernel<<<T / BM, THREADS, SMEM_BYTES>>>(x, nw, noise, out, T, write_idx);
}

// round 8
// speedup vs baseline: 2.2283x; 1.0457x over previous
#include <cuda_runtime.h>
#include <cuda_fp16.h>
#include <math.h>
#include <stdint.h>

#define TD 1024
#define TE 64
#define BM 64            // tokens per CTA (grid = 256)
#define THREADS 256

// smem layout:
//   Cs [64][66] f32            : 0 .. 16896
//   w1s/w2s/i1s/i2s (64 each)  : 16896 .. 17920
//   noiseS [64][64] f32        : 17920 .. 34304
//   nws [64] f32               : 34304 .. 34560
#define CS_OFF    0
#define CS_STRIDE 66
#define W1_OFF    16896
#define W2_OFF    17152
#define I1_OFF    17408
#define I2_OFF    17664
#define NZ_OFF    17920
#define NW_OFF    34304
#define SMEM_BYTES 34560

typedef unsigned int u32;

// W in fragment order: [kstep][term][n8tile][lane] -> uint2{b0,b1}; 64*2*8*32 = 32768
__device__ uint2 g_wfrag[32768];

// 2 floats -> 2 packed fp16x2 terms (hi, residual-lo)
__device__ __forceinline__ void split2(float vl, float vh, u32& t0, u32& t1) {
    __half2 h0 = __floats2half2_rn(vl, vh);
    float2 f0 = __half22float2(h0);
    __half2 h1 = __floats2half2_rn(vl - f0.x, vh - f0.y);
    t0 = *reinterpret_cast<u32*>(&h0);
    t1 = *reinterpret_cast<u32*>(&h1);
}
__device__ __forceinline__ void mma16816(float* c, const u32* A, u32 b0, u32 b1) {
    asm volatile(
        "mma.sync.aligned.m16n8k16.row.col.f32.f16.f16.f32 "
        "{%0,%1,%2,%3}, {%4,%5,%6,%7}, {%8,%9}, {%0,%1,%2,%3};"
        : "+f"(c[0]), "+f"(c[1]), "+f"(c[2]), "+f"(c[3])
        : "r"(A[0]), "r"(A[1]), "r"(A[2]), "r"(A[3]), "r"(b0), "r"(b1));
}

// ---------------- pre-kernel: W fp32 -> fp16x2 fragments ----------------
__global__ void __launch_bounds__(256) wconv_kernel(const float* __restrict__ gw) {
    int t = blockIdx.x * 256 + threadIdx.x;     // 0..16383
    int ks   = t >> 8;
    int nt   = (t >> 5) & 7;
    int lane = t & 31;
    int n  = nt * 8 + (lane >> 2);
    int k0 = ks * 16 + 2 * (lane & 3);
    const float* wp = gw + n * TD + k0;
    float2 p0 = *reinterpret_cast<const float2*>(wp);       // k0, k0+1
    float2 p1 = *reinterpret_cast<const float2*>(wp + 8);   // k0+8, k0+9
    u32 b0t0, b0t1, b1t0, b1t1;
    split2(p0.x, p0.y, b0t0, b0t1);
    split2(p1.x, p1.y, b1t0, b1t1);
    int base = ks * 512 + nt * 32 + lane;
    g_wfrag[base]       = make_uint2(b0t0, b1t0);   // term 0 (hi)
    g_wfrag[base + 256] = make_uint2(b0t1, b1t1);   // term 1 (lo)
}

// ---------------- main fused kernel ----------------
__global__ void __launch_bounds__(THREADS, 2) gate_kernel(
    const float* __restrict__ x,      // [T, 1024]
    const float* __restrict__ nw,     // [64]
    const float* __restrict__ noise,  // [T, 64]
    float* __restrict__ out,
    int T, int write_idx)
{
    extern __shared__ char smem[];
    const int tid  = threadIdx.x;
    const int lane = tid & 31;
    const int wid  = tid >> 5;
    const int mtw  = wid & 3;          // token group: tokens mtw*16..+15
    const int kh   = wid >> 2;         // k half: ksteps kh*32..+31
    const long long t0 = (long long)blockIdx.x * BM;

    // --- stage noise + nw into smem (hides epilogue tail) ---
    {
        const float4* np = reinterpret_cast<const float4*>(noise + t0 * TE);
        float4* ns = reinterpret_cast<float4*>(smem + NZ_OFF);
        #pragma unroll
        for (int u = 0; u < 4; u++) ns[u * 256 + tid] = np[u * 256 + tid];
        if (tid < TE) reinterpret_cast<float*>(smem + NW_OFF)[tid] = nw[tid];
    }

    const int kb = kh * 32;            // base kstep for this warp
    // A source: lane covers rows (mtw*16 + lane/4) and +8, k pairs at 2*(lane&3), +8
    const float* xA = x + (t0 + mtw * 16 + (lane >> 2)) * TD + kb * 16 + 2 * (lane & 3);
    const uint2* bp = g_wfrag + lane;

    float acc[8][4];
    #pragma unroll
    for (int i = 0; i < 8; i++)
        #pragma unroll
        for (int j = 0; j < 4; j++) acc[i][j] = 0.0f;

    float2 ar[4];
    uint2  br[2][8];

    // load k-step kb
    ar[0] = *reinterpret_cast<const float2*>(xA);
    ar[1] = *reinterpret_cast<const float2*>(xA + 8);
    ar[2] = *reinterpret_cast<const float2*>(xA + 8 * TD);
    ar[3] = *reinterpret_cast<const float2*>(xA + 8 * TD + 8);
    #pragma unroll
    for (int t = 0; t < 2; t++)
        #pragma unroll
        for (int j = 0; j < 8; j++) br[t][j] = bp[kb * 512 + t * 256 + j * 32];

    #pragma unroll 2
    for (int ks = 0; ks < 32; ks++) {
        const int nks = (ks + 1) & 31;          // relative next step (wraps; harmless)
        // prefetch next A
        float2 an[4];
        {
            const float* xp = xA + nks * 16;
            an[0] = *reinterpret_cast<const float2*>(xp);
            an[1] = *reinterpret_cast<const float2*>(xp + 8);
            an[2] = *reinterpret_cast<const float2*>(xp + 8 * TD);
            an[3] = *reinterpret_cast<const float2*>(xp + 8 * TD + 8);
        }
        // convert current A to fp16x2 fragments (both terms)
        u32 aF[2][4];
        split2(ar[0].x, ar[0].y, aF[0][0], aF[1][0]);
        split2(ar[2].x, ar[2].y, aF[0][1], aF[1][1]);
        split2(ar[1].x, ar[1].y, aF[0][2], aF[1][2]);
        split2(ar[3].x, ar[3].y, aF[0][3], aF[1][3]);

        const uint2* bq = bp + (kb + nks) * 512;
        // pass1: hh
        #pragma unroll
        for (int nt = 0; nt < 8; nt++) mma16816(acc[nt], aF[0], br[0][nt].x, br[0][nt].y);
        // pass2: lh (last use of br[0])
        #pragma unroll
        for (int nt = 0; nt < 8; nt++) mma16816(acc[nt], aF[1], br[0][nt].x, br[0][nt].y);
        // reload br[0] for next step (in-place prefetch)
        #pragma unroll
        for (int j = 0; j < 8; j++) br[0][j] = bq[j * 32];
        // pass3: hl (last use of br[1])
        #pragma unroll
        for (int nt = 0; nt < 8; nt++) mma16816(acc[nt], aF[0], br[1][nt].x, br[1][nt].y);
        // reload br[1]
        #pragma unroll
        for (int j = 0; j < 8; j++) br[1][j] = bq[256 + j * 32];
        // rotate A
        #pragma unroll
        for (int i = 0; i < 4; i++) ar[i] = an[i];
    }

    // ---------------- split-K reduction + epilogue ----------------
    float* Cs  = reinterpret_cast<float*>(smem + CS_OFF);
    float* w1s = reinterpret_cast<float*>(smem + W1_OFF);
    float* w2s = reinterpret_cast<float*>(smem + W2_OFF);
    int*   i1s = reinterpret_cast<int*>(smem + I1_OFF);
    int*   i2s = reinterpret_cast<int*>(smem + I2_OFF);
    const float* nzS  = reinterpret_cast<const float*>(smem + NZ_OFF);
    const float* nwsS = reinterpret_cast<const float*>(smem + NW_OFF);

    const int g  = lane >> 2, tq = lane & 3;
    const int r0 = mtw * 16 + g;

    // warps 4-7 (kh=1) store their partial first
    if (kh == 1) {
        #pragma unroll
        for (int nt = 0; nt < 8; nt++) {
            int col = nt * 8 + 2 * tq;
            *reinterpret_cast<float2*>(&Cs[r0 * CS_STRIDE + col])       = make_float2(acc[nt][0], acc[nt][1]);
            *reinterpret_cast<float2*>(&Cs[(r0 + 8) * CS_STRIDE + col]) = make_float2(acc[nt][2], acc[nt][3]);
        }
    }
    __syncthreads();
    // warps 0-3 add theirs
    if (kh == 0) {
        #pragma unroll
        for (int nt = 0; nt < 8; nt++) {
            int col = nt * 8 + 2 * tq;
            float2* p0 = reinterpret_cast<float2*>(&Cs[r0 * CS_STRIDE + col]);
            float2* p1 = reinterpret_cast<float2*>(&Cs[(r0 + 8) * CS_STRIDE + col]);
            float2 v0 = *p0, v1 = *p1;
            v0.x += acc[nt][0]; v0.y += acc[nt][1];
            v1.x += acc[nt][2]; v1.y += acc[nt][3];
            *p0 = v0; *p1 = v1;
        }
    }
    __syncthreads();

    if (tid < BM) {
        const float* rowp = Cs + tid * CS_STRIDE;
        const float* nr   = nzS + tid * TE;
        float v1 = -3.402823466e38f, v2 = -3.402823466e38f;
        int i1 = 0, i2 = 0;
        #pragma unroll
        for (int e = 0; e < TE; e++) {
            float v = rowp[e] + nr[e] * nwsS[e];
            if (v > v1)      { v2 = v1; i2 = i1; v1 = v; i1 = e; }
            else if (v > v2) { v2 = v;  i2 = e; }
        }
        float e2 = expf(v2 - v1);
        float sm = 1.0f + e2;
        w1s[tid] = 1.0f / sm;
        w2s[tid] = e2 / sm;
        i1s[tid] = i1;
        i2s[tid] = i2;
    }
    __syncthreads();

    // coalesced weight scatter: 64*64 floats = 1024 float4
    float4* o4 = reinterpret_cast<float4*>(out + t0 * TE);
    #pragma unroll
    for (int u = 0; u < 4; u++) {
        int idx = u * 256 + tid;
        int m  = idx >> 4;
        int e0 = (idx & 15) << 2;
        int i1 = i1s[m], i2 = i2s[m];
        float w1 = w1s[m], w2 = w2s[m];
        float4 o;
        o.x = (i1 == e0    ) ? w1 : (i2 == e0    ) ? w2 : 0.0f;
        o.y = (i1 == e0 + 1) ? w1 : (i2 == e0 + 1) ? w2 : 0.0f;
        o.z = (i1 == e0 + 2) ? w1 : (i2 == e0 + 2) ? w2 : 0.0f;
        o.w = (i1 == e0 + 3) ? w1 : (i2 == e0 + 3) ? w2 : 0.0f;
        o4[idx] = o;
    }
    if (write_idx && tid < BM) {
        long long t = t0 + tid;
        float* oi = out + (size_t)T * TE;
        oi[t * 2 + 0] = (float)i1s[tid];
        oi[t * 2 + 1] = (float)i2s[tid];
    }
}

extern "C" void kernel_launch(void* const* d_in, const int* in_sizes, int n_in,
                              void* d_out, int out_size) {
    const float* x     = (const float*)d_in[0];
    const float* gw    = (const float*)d_in[1];
    const float* nw    = (const float*)d_in[2];
    const float* noise = (const float*)d_in[3];
    float* out = (float*)d_out;

    int T = in_sizes[0] / TD;                       // 16384
    int write_idx = (out_size >= T * TE + T * 2) ? 1 : 0;

    wconv_kernel<<<64, 256>>>(gw);
    gate_kernel<<<T / BM, THREADS, SMEM_BYTES>>>(x, nw, noise, out, T, write_idx);
}